// round 12
// baseline (speedup 1.0000x reference)
#include <cuda_runtime.h>

#define BATCH 1024
#define FDIM 32
#define EMBED 8
#define HEADS 4
#define NBINS 1100
#define OUTD 16
#define FH (FDIM*HEADS)

typedef unsigned long long u64;

// Scratch (allocation-free: __device__ globals)
__device__ float2 g_q[FH * BATCH];
__device__ float2 g_k[FH * BATCH];
__device__ float2 g_v[FH * BATCH];
__device__ float g_o[BATCH * FDIM * EMBED];   // [B][256]

// ---- packed f32x2 helpers (Blackwell FFMA2 path, PTX-only) -----------------
__device__ __forceinline__ u64 pk(float lo, float hi) {
    u64 r; asm("mov.b64 %0, {%1, %2};" : "=l"(r) : "f"(lo), "f"(hi)); return r;
}
__device__ __forceinline__ void upk(u64 a, float& x, float& y) {
    asm("mov.b64 {%0, %1}, %2;" : "=f"(x), "=f"(y) : "l"(a));
}
__device__ __forceinline__ u64 fma2(u64 a, u64 b, u64 c) {
    u64 d; asm("fma.rn.f32x2 %0, %1, %2, %3;" : "=l"(d) : "l"(a), "l"(b), "l"(c)); return d;
}
__device__ __forceinline__ u64 mul2(u64 a, u64 b) {
    u64 d; asm("mul.rn.f32x2 %0, %1, %2;" : "=l"(d) : "l"(a), "l"(b)); return d;
}
__device__ __forceinline__ u64 add2(u64 a, u64 b) {
    u64 d; asm("add.rn.f32x2 %0, %1, %2;" : "=l"(d) : "l"(a), "l"(b)); return d;
}
__device__ __forceinline__ float ex2f(float s) {
    float e; asm("ex2.approx.ftz.f32 %0, %1;" : "=f"(e) : "f"(s)); return e;
}

// Packed exp2 on the FMA pipe: 8 packed FMA-pipe ops + 4 ALU ops per 2 exps.
__device__ __forceinline__ u64 exp2_poly2(u64 x) {
    const float MAGIC = 12582912.0f;            // 2^23 + 2^22
    u64 t = add2(x, pk(MAGIC, MAGIC));          // n captured in mantissa
    u64 u = add2(t, pk(-MAGIC, -MAGIC));        // u = round(x)
    u64 r = fma2(u, pk(-1.0f, -1.0f), x);       // r = x - u, |r| <= 0.5
    u64 p = fma2(pk(0.00961813f, 0.00961813f), r, pk(0.05550411f, 0.05550411f));
    p = fma2(p, r, pk(0.24022651f, 0.24022651f));
    p = fma2(p, r, pk(0.69314718f, 0.69314718f));
    p = fma2(p, r, pk(1.0f, 1.0f));
    float tlo, thi; upk(t, tlo, thi);
    unsigned ilo = (__float_as_uint(tlo) << 23) + (127u << 23);   // bits of 2^n_lo
    unsigned ihi = (__float_as_uint(thi) << 23) + (127u << 23);
    return mul2(p, pk(__uint_as_float(ilo), __uint_as_float(ihi)));
}

// Replicate jnp.linspace(MN,MX,NBINS) element: step*i + start, fp32 rounding
// at each op (no FMA contraction).
__device__ __forceinline__ float binv(int i) {
    const float step = 301.0f / 1099.0f;
    return __fadd_rn(__fmul_rn(step, (float)i), -1.0f);
}

// ---------------------------------------------------------------------------
// Stage A: bin search + embedding gather + QKV projection.
// grid (4, 32) x 256 (best measured ~6.0us)
// ---------------------------------------------------------------------------
__global__ void stageA(const float* __restrict__ x, const float* __restrict__ emb,
                       const float* __restrict__ ipw, const float* __restrict__ ipb) {
    __shared__ float sw[192];
    __shared__ float sb[24];
    int tid = threadIdx.x;
    if (tid < 192) sw[tid] = ipw[tid];
    if (tid < 24)  sb[tid] = ipb[tid];
    __syncthreads();

    int f = blockIdx.y;
    int b = blockIdx.x * blockDim.x + tid;

    float xv = x[b * FDIM + f];
    float xc = fminf(fmaxf(xv, -1.0f), 300.0f);

    // searchsorted(bins, xc, 'left'): first i with bins[i] >= xc
    int i = (int)((xc + 1.0f) * (1099.0f / 301.0f));
    i = max(0, min(i, NBINS - 1));
    while (i > 0 && binv(i - 1) >= xc) --i;
    while (i < NBINS - 1 && binv(i) < xc) ++i;

    const float4* ep = (const float4*)(emb + ((size_t)f * NBINS + i) * EMBED);
    float4 e0 = ep[0], e1 = ep[1];
    float xe[8] = {e0.x, e0.y, e0.z, e0.w, e1.x, e1.y, e1.z, e1.w};

    float out[24];
#pragma unroll
    for (int r = 0; r < 24; ++r) {
        float acc = sb[r];
#pragma unroll
        for (int j = 0; j < 8; ++j) acc = fmaf(xe[j], sw[r * 8 + j], acc);
        out[r] = acc;
    }

#pragma unroll
    for (int h = 0; h < HEADS; ++h) {
        int o = (f * HEADS + h) * BATCH + b;
        g_q[o] = make_float2(out[h * 2],      out[h * 2 + 1]);
        g_k[o] = make_float2(out[8 + h * 2],  out[8 + h * 2 + 1]);
        g_v[o] = make_float2(out[16 + h * 2], out[16 + h * 2 + 1]);
    }
}

// ---------------------------------------------------------------------------
// Stage B: per-(f,h) attention, hd=2, single-pass softmax.
// 2-b register tiling (each LDS pair serves b and b+512) + 1/4 of pairs' exps
// on the FMA-pipe polynomial. grid (128, 8) x 64 = 1024 blocks -- divisible
// placement (ceil/avg = +1.2%), which R11 showed is the variable that matters.
// ---------------------------------------------------------------------------
__global__ void __launch_bounds__(64) stageB() {
    __shared__ ulonglong2 sA[BATCH / 2];   // 8KB: K pairs
    __shared__ ulonglong2 sB[BATCH / 2];   // 8KB: V pairs
    int fh  = blockIdx.x;
    int tid = threadIdx.x;

    const float4* kp = (const float4*)(g_k + fh * BATCH);  // (k0e,k1e,k0o,k1o)
    const float4* vp = (const float4*)(g_v + fh * BATCH);
#pragma unroll
    for (int p = tid; p < BATCH / 2; p += 64) {
        float4 k = kp[p];
        float4 v = vp[p];
        sA[p] = make_ulonglong2(pk(k.x, k.z), pk(k.y, k.w));
        sB[p] = make_ulonglong2(pk(v.x, v.z), pk(v.y, v.w));
    }
    __syncthreads();

    int b0 = blockIdx.y * 64 + tid;      // 0..511
    int b1 = b0 + 512;
    float2 qa = g_q[fh * BATCH + b0];
    float2 qb = g_q[fh * BATCH + b1];
    // fold 1/sqrt(hd) and log2(e) into q so exp(s) == exp2(q'.k)
    const float C = 1.4426950408889634f * 0.70710678118654752f;
    u64 qa0 = pk(qa.x * C, qa.x * C), qa1 = pk(qa.y * C, qa.y * C);
    u64 qb0 = pk(qb.x * C, qb.x * C), qb1 = pk(qb.y * C, qb.y * C);
    u64 z = pk(0.f, 0.f);
    u64 dA = z, aA0 = z, aA1 = z;
    u64 dB = z, aB0 = z, aB1 = z;

    for (int pb = 0; pb < BATCH / 2; pb += 4) {
        // pair 0: exps for BOTH b's on the FMA pipe (branch-free structural)
        {
            ulonglong2 A  = sA[pb];
            ulonglong2 Bv = sB[pb];
            u64 eA = exp2_poly2(fma2(qa0, A.x, mul2(qa1, A.y)));
            u64 eB = exp2_poly2(fma2(qb0, A.x, mul2(qb1, A.y)));
            dA  = add2(dA, eA);
            aA0 = fma2(eA, Bv.x, aA0);
            aA1 = fma2(eA, Bv.y, aA1);
            dB  = add2(dB, eB);
            aB0 = fma2(eB, Bv.x, aB0);
            aB1 = fma2(eB, Bv.y, aB1);
        }
        // pairs 1..3: exps on MUFU
#pragma unroll
        for (int j = 1; j < 4; ++j) {
            ulonglong2 A  = sA[pb + j];
            ulonglong2 Bv = sB[pb + j];
            u64 ssA = fma2(qa0, A.x, mul2(qa1, A.y));
            u64 ssB = fma2(qb0, A.x, mul2(qb1, A.y));
            float sa0, sa1, sb0, sb1;
            upk(ssA, sa0, sa1);
            upk(ssB, sb0, sb1);
            u64 eA = pk(ex2f(sa0), ex2f(sa1));
            u64 eB = pk(ex2f(sb0), ex2f(sb1));
            dA  = add2(dA, eA);
            aA0 = fma2(eA, Bv.x, aA0);
            aA1 = fma2(eA, Bv.y, aA1);
            dB  = add2(dB, eB);
            aB0 = fma2(eB, Bv.x, aB0);
            aB1 = fma2(eB, Bv.y, aB1);
        }
    }

    int f = fh >> 2, h = fh & 3;
    {
        float d0, d1, a00, a01, a10, a11;
        upk(dA, d0, d1); upk(aA0, a00, a01); upk(aA1, a10, a11);
        float inv = 1.0f / (d0 + d1);
        float* op = g_o + (size_t)b0 * (FDIM * EMBED) + f * EMBED + h * 2;
        op[0] = (a00 + a01) * inv;
        op[1] = (a10 + a11) * inv;
    }
    {
        float d0, d1, a00, a01, a10, a11;
        upk(dB, d0, d1); upk(aB0, a00, a01); upk(aB1, a10, a11);
        float inv = 1.0f / (d0 + d1);
        float* op = g_o + (size_t)b1 * (FDIM * EMBED) + f * EMBED + h * 2;
        op[0] = (a00 + a01) * inv;
        op[1] = (a10 + a11) * inv;
    }
}

// ---------------------------------------------------------------------------
// Stage C: out_proj (8x8 per f) + linear (16x256) + softmax(16).
// grid 64 x 256: one thread per output element in phase 2 (R9 version).
// ---------------------------------------------------------------------------
__global__ void stageC(const float* __restrict__ opw, const float* __restrict__ opb,
                       const float* __restrict__ lw,  const float* __restrict__ lb,
                       float* __restrict__ out) {
    __shared__ float sWo[64];
    __shared__ float sbo[8];
    __shared__ float sLb[16];
    __shared__ __align__(16) float4 sLwT[64][16];   // [i4][t] = lw[t][4*i4..]
    __shared__ __align__(16) float o2sh[16][264];   // 264: float4-aligned rows

    int tid = threadIdx.x;
    for (int idx = tid; idx < 1024; idx += 256) {
        int t = idx & 15, i4 = idx >> 4;
        sLwT[i4][t] = ((const float4*)lw)[t * 64 + i4];
    }
    if (tid < 64) sWo[tid] = opw[tid];
    if (tid < 8)  sbo[tid] = opb[tid];
    if (tid < 16) sLb[tid] = lb[tid];
    __syncthreads();

    // Phase 1: o2 = o @ Wo^T + bo for this block's 16 b. 512 (bl,f) items.
#pragma unroll
    for (int it = tid; it < 512; it += 256) {
        int bl = it >> 5, f = it & 31;
        int b = blockIdx.x * 16 + bl;
        const float4* op4 = (const float4*)(g_o + (size_t)b * 256 + f * 8);
        float4 v0 = op4[0], v1 = op4[1];
        float o[8] = {v0.x, v0.y, v0.z, v0.w, v1.x, v1.y, v1.z, v1.w};
        float r[8];
#pragma unroll
        for (int e = 0; e < 8; ++e) {
            float acc = sbo[e];
#pragma unroll
            for (int j = 0; j < 8; ++j) acc = fmaf(o[j], sWo[e * 8 + j], acc);
            r[e] = acc;
        }
        float4* dst = (float4*)&o2sh[bl][f * 8];
        dst[0] = make_float4(r[0], r[1], r[2], r[3]);
        dst[1] = make_float4(r[4], r[5], r[6], r[7]);
    }
    __syncthreads();

    // Phase 2: one output per thread: logits[b][t] = o2[b] . lw[t] + lb[t]
    int bl = tid >> 4, t = tid & 15;
    const float4* orow = (const float4*)&o2sh[bl][0];
    float a0 = 0.f, a1 = 0.f, a2 = 0.f, a3 = 0.f;
#pragma unroll 16
    for (int i4 = 0; i4 < 64; ++i4) {
        float4 ov = orow[i4];
        float4 wv = sLwT[i4][t];
        a0 = fmaf(ov.x, wv.x, a0);
        a1 = fmaf(ov.y, wv.y, a1);
        a2 = fmaf(ov.z, wv.z, a2);
        a3 = fmaf(ov.w, wv.w, a3);
    }
    float acc = sLb[t] + ((a0 + a1) + (a2 + a3));

    // softmax over the 16 t's (width-16 shfl groups; 2 groups per warp)
    float m = acc;
#pragma unroll
    for (int off = 8; off; off >>= 1)
        m = fmaxf(m, __shfl_xor_sync(0xffffffffu, m, off, 16));
    float e = __expf(acc - m);
    float s = e;
#pragma unroll
    for (int off = 8; off; off >>= 1)
        s += __shfl_xor_sync(0xffffffffu, s, off, 16);

    int b = blockIdx.x * 16 + bl;
    out[b * OUTD + t] = e / s;
}

// ---------------------------------------------------------------------------
extern "C" void kernel_launch(void* const* d_in, const int* in_sizes, int n_in,
                              void* d_out, int out_size) {
    const float* x   = (const float*)d_in[0];   // (1024, 32)
    const float* emb = (const float*)d_in[1];   // (32, 1100, 8)
    const float* ipw = (const float*)d_in[2];   // (24, 8)
    const float* ipb = (const float*)d_in[3];   // (24,)
    const float* opw = (const float*)d_in[4];   // (8, 8)
    const float* opb = (const float*)d_in[5];   // (8,)
    const float* lw  = (const float*)d_in[6];   // (16, 256)
    const float* lb  = (const float*)d_in[7];   // (16,)
    float* out = (float*)d_out;                 // (1024, 16)

    stageA<<<dim3(4, FDIM), 256>>>(x, emb, ipw, ipb);
    stageB<<<dim3(FH, 8), 64>>>();
    stageC<<<BATCH / 16, 256>>>(opw, opb, lw, lb, out);
}

// round 13
// speedup vs baseline: 1.1797x; 1.1797x over previous
#include <cuda_runtime.h>

#define BATCH 1024
#define FDIM 32
#define EMBED 8
#define HEADS 4
#define NBINS 1100
#define OUTD 16
#define FH (FDIM*HEADS)

typedef unsigned long long u64;

// Scratch (allocation-free: __device__ globals)
__device__ float2 g_q[FH * BATCH];
__device__ float2 g_k[FH * BATCH];
__device__ float2 g_v[FH * BATCH];
__device__ float g_o[BATCH * FDIM * EMBED];   // [B][256]

// ---- packed f32x2 helpers (Blackwell FFMA2 path, PTX-only) -----------------
__device__ __forceinline__ u64 pk(float lo, float hi) {
    u64 r; asm("mov.b64 %0, {%1, %2};" : "=l"(r) : "f"(lo), "f"(hi)); return r;
}
__device__ __forceinline__ void upk(u64 a, float& x, float& y) {
    asm("mov.b64 {%0, %1}, %2;" : "=f"(x), "=f"(y) : "l"(a));
}
__device__ __forceinline__ u64 fma2(u64 a, u64 b, u64 c) {
    u64 d; asm("fma.rn.f32x2 %0, %1, %2, %3;" : "=l"(d) : "l"(a), "l"(b), "l"(c)); return d;
}
__device__ __forceinline__ u64 mul2(u64 a, u64 b) {
    u64 d; asm("mul.rn.f32x2 %0, %1, %2;" : "=l"(d) : "l"(a), "l"(b)); return d;
}
__device__ __forceinline__ u64 add2(u64 a, u64 b) {
    u64 d; asm("add.rn.f32x2 %0, %1, %2;" : "=l"(d) : "l"(a), "l"(b)); return d;
}
__device__ __forceinline__ float ex2f(float s) {
    float e; asm("ex2.approx.ftz.f32 %0, %1;" : "=f"(e) : "f"(s)); return e;
}

// Packed exp2 on the FMA pipe: 8 packed FMA-pipe ops + 4 ALU ops per 2 exps.
__device__ __forceinline__ u64 exp2_poly2(u64 x) {
    const float MAGIC = 12582912.0f;            // 2^23 + 2^22
    u64 t = add2(x, pk(MAGIC, MAGIC));          // n captured in mantissa
    u64 u = add2(t, pk(-MAGIC, -MAGIC));        // u = round(x)
    u64 r = fma2(u, pk(-1.0f, -1.0f), x);       // r = x - u, |r| <= 0.5
    u64 p = fma2(pk(0.00961813f, 0.00961813f), r, pk(0.05550411f, 0.05550411f));
    p = fma2(p, r, pk(0.24022651f, 0.24022651f));
    p = fma2(p, r, pk(0.69314718f, 0.69314718f));
    p = fma2(p, r, pk(1.0f, 1.0f));
    float tlo, thi; upk(t, tlo, thi);
    unsigned ilo = (__float_as_uint(tlo) << 23) + (127u << 23);   // bits of 2^n_lo
    unsigned ihi = (__float_as_uint(thi) << 23) + (127u << 23);
    return mul2(p, pk(__uint_as_float(ilo), __uint_as_float(ihi)));
}

// Replicate jnp.linspace(MN,MX,NBINS) element: step*i + start, fp32 rounding
// at each op (no FMA contraction).
__device__ __forceinline__ float binv(int i) {
    const float step = 301.0f / 1099.0f;
    return __fadd_rn(__fmul_rn(step, (float)i), -1.0f);
}

// ---------------------------------------------------------------------------
// Stage A: bin search + embedding gather + QKV projection.
// grid (4, 32) x 256 (best measured ~6.0us)
// ---------------------------------------------------------------------------
__global__ void stageA(const float* __restrict__ x, const float* __restrict__ emb,
                       const float* __restrict__ ipw, const float* __restrict__ ipb) {
    __shared__ float sw[192];
    __shared__ float sb[24];
    int tid = threadIdx.x;
    if (tid < 192) sw[tid] = ipw[tid];
    if (tid < 24)  sb[tid] = ipb[tid];
    __syncthreads();

    int f = blockIdx.y;
    int b = blockIdx.x * blockDim.x + tid;

    float xv = x[b * FDIM + f];
    float xc = fminf(fmaxf(xv, -1.0f), 300.0f);

    // searchsorted(bins, xc, 'left'): first i with bins[i] >= xc
    int i = (int)((xc + 1.0f) * (1099.0f / 301.0f));
    i = max(0, min(i, NBINS - 1));
    while (i > 0 && binv(i - 1) >= xc) --i;
    while (i < NBINS - 1 && binv(i) < xc) ++i;

    const float4* ep = (const float4*)(emb + ((size_t)f * NBINS + i) * EMBED);
    float4 e0 = ep[0], e1 = ep[1];
    float xe[8] = {e0.x, e0.y, e0.z, e0.w, e1.x, e1.y, e1.z, e1.w};

    float out[24];
#pragma unroll
    for (int r = 0; r < 24; ++r) {
        float acc = sb[r];
#pragma unroll
        for (int j = 0; j < 8; ++j) acc = fmaf(xe[j], sw[r * 8 + j], acc);
        out[r] = acc;
    }

#pragma unroll
    for (int h = 0; h < HEADS; ++h) {
        int o = (f * HEADS + h) * BATCH + b;
        g_q[o] = make_float2(out[h * 2],      out[h * 2 + 1]);
        g_k[o] = make_float2(out[8 + h * 2],  out[8 + h * 2 + 1]);
        g_v[o] = make_float2(out[16 + h * 2], out[16 + h * 2 + 1]);
    }
}

// ---------------------------------------------------------------------------
// Stage B: per-(f,h) attention, hd=2, single-pass softmax (R6/R9 exact:
// measured-best). PDL: gridsync before touching stage A's outputs.
// grid (128, 8) x 128.
// ---------------------------------------------------------------------------
__global__ void stageB() {
    __shared__ ulonglong2 sA[BATCH / 2];   // 8KB
    __shared__ ulonglong2 sB[BATCH / 2];   // 8KB
    int fh  = blockIdx.x;
    int tid = threadIdx.x;

    cudaGridDependencySynchronize();       // wait for stage A's writes

    const float4* kp = (const float4*)(g_k + fh * BATCH);  // (k0e,k1e,k0o,k1o)
    const float4* vp = (const float4*)(g_v + fh * BATCH);
    for (int p = tid; p < BATCH / 2; p += 128) {
        float4 k = kp[p];
        float4 v = vp[p];
        sA[p] = make_ulonglong2(pk(k.x, k.z), pk(k.y, k.w));
        sB[p] = make_ulonglong2(pk(v.x, v.z), pk(v.y, v.w));
    }
    __syncthreads();

    int b = blockIdx.y * 128 + tid;
    float2 q = g_q[fh * BATCH + b];
    const float C = 1.4426950408889634f * 0.70710678118654752f;
    float q0 = q.x * C, q1 = q.y * C;
    u64 qq0 = pk(q0, q0), qq1 = pk(q1, q1);
    u64 dd = pk(0.f, 0.f), aa0 = dd, aa1 = dd;

    for (int pb = 0; pb < BATCH / 2; pb += 8) {
        {
            ulonglong2 A  = sA[pb];
            ulonglong2 Bv = sB[pb];
            u64 ee = exp2_poly2(fma2(qq0, A.x, mul2(qq1, A.y)));
            dd  = add2(dd, ee);
            aa0 = fma2(ee, Bv.x, aa0);
            aa1 = fma2(ee, Bv.y, aa1);
        }
#pragma unroll
        for (int j = 1; j < 8; ++j) {
            ulonglong2 A  = sA[pb + j];
            ulonglong2 Bv = sB[pb + j];
            u64 ss = fma2(qq0, A.x, mul2(qq1, A.y));
            float s0, s1; upk(ss, s0, s1);
            u64 ee = pk(ex2f(s0), ex2f(s1));
            dd  = add2(dd, ee);
            aa0 = fma2(ee, Bv.x, aa0);
            aa1 = fma2(ee, Bv.y, aa1);
        }
    }

    float d0, d1, a00, a01, a10, a11;
    upk(dd, d0, d1); upk(aa0, a00, a01); upk(aa1, a10, a11);
    float inv = 1.0f / (d0 + d1);
    int f = fh >> 2, h = fh & 3;
    float* op = g_o + (size_t)b * (FDIM * EMBED) + f * EMBED + h * 2;
    op[0] = (a00 + a01) * inv;
    op[1] = (a10 + a11) * inv;
}

// ---------------------------------------------------------------------------
// Stage C: out_proj + linear + softmax (R9 version).
// PDL: loads all weights to smem BEFORE gridsync -> overlaps stage B's tail.
// grid 64 x 256.
// ---------------------------------------------------------------------------
__global__ void stageC(const float* __restrict__ opw, const float* __restrict__ opb,
                       const float* __restrict__ lw,  const float* __restrict__ lb,
                       float* __restrict__ out) {
    __shared__ float sWo[64];
    __shared__ float sbo[8];
    __shared__ float sLb[16];
    __shared__ __align__(16) float4 sLwT[64][16];   // [i4][t] = lw[t][4*i4..]
    __shared__ __align__(16) float o2sh[16][264];   // 264: float4-aligned rows

    int tid = threadIdx.x;
    // ---- pre-dependency prolog: weight staging (overlaps stage B) ----
    for (int idx = tid; idx < 1024; idx += 256) {
        int t = idx & 15, i4 = idx >> 4;
        sLwT[i4][t] = ((const float4*)lw)[t * 64 + i4];
    }
    if (tid < 64) sWo[tid] = opw[tid];
    if (tid < 8)  sbo[tid] = opb[tid];
    if (tid < 16) sLb[tid] = lb[tid];

    cudaGridDependencySynchronize();       // wait for stage B's g_o writes
    __syncthreads();

    // Phase 1: o2 = o @ Wo^T + bo for this block's 16 b. 512 (bl,f) items.
#pragma unroll
    for (int it = tid; it < 512; it += 256) {
        int bl = it >> 5, f = it & 31;
        int b = blockIdx.x * 16 + bl;
        const float4* op4 = (const float4*)(g_o + (size_t)b * 256 + f * 8);
        float4 v0 = op4[0], v1 = op4[1];
        float o[8] = {v0.x, v0.y, v0.z, v0.w, v1.x, v1.y, v1.z, v1.w};
        float r[8];
#pragma unroll
        for (int e = 0; e < 8; ++e) {
            float acc = sbo[e];
#pragma unroll
            for (int j = 0; j < 8; ++j) acc = fmaf(o[j], sWo[e * 8 + j], acc);
            r[e] = acc;
        }
        float4* dst = (float4*)&o2sh[bl][f * 8];
        dst[0] = make_float4(r[0], r[1], r[2], r[3]);
        dst[1] = make_float4(r[4], r[5], r[6], r[7]);
    }
    __syncthreads();

    // Phase 2: one output per thread: logits[b][t] = o2[b] . lw[t] + lb[t]
    int bl = tid >> 4, t = tid & 15;
    const float4* orow = (const float4*)&o2sh[bl][0];
    float a0 = 0.f, a1 = 0.f, a2 = 0.f, a3 = 0.f;
#pragma unroll 16
    for (int i4 = 0; i4 < 64; ++i4) {
        float4 ov = orow[i4];
        float4 wv = sLwT[i4][t];
        a0 = fmaf(ov.x, wv.x, a0);
        a1 = fmaf(ov.y, wv.y, a1);
        a2 = fmaf(ov.z, wv.z, a2);
        a3 = fmaf(ov.w, wv.w, a3);
    }
    float acc = sLb[t] + ((a0 + a1) + (a2 + a3));

    // softmax over the 16 t's (width-16 shfl groups; 2 groups per warp)
    float m = acc;
#pragma unroll
    for (int off = 8; off; off >>= 1)
        m = fmaxf(m, __shfl_xor_sync(0xffffffffu, m, off, 16));
    float e = __expf(acc - m);
    float s = e;
#pragma unroll
    for (int off = 8; off; off >>= 1)
        s += __shfl_xor_sync(0xffffffffu, s, off, 16);

    int b = blockIdx.x * 16 + bl;
    out[b * OUTD + t] = e / s;
}

// ---------------------------------------------------------------------------
extern "C" void kernel_launch(void* const* d_in, const int* in_sizes, int n_in,
                              void* d_out, int out_size) {
    const float* x   = (const float*)d_in[0];   // (1024, 32)
    const float* emb = (const float*)d_in[1];   // (32, 1100, 8)
    const float* ipw = (const float*)d_in[2];   // (24, 8)
    const float* ipb = (const float*)d_in[3];   // (24,)
    const float* opw = (const float*)d_in[4];   // (8, 8)
    const float* opb = (const float*)d_in[5];   // (8,)
    const float* lw  = (const float*)d_in[6];   // (16, 256)
    const float* lb  = (const float*)d_in[7];   // (16,)
    float* out = (float*)d_out;                 // (1024, 16)

    stageA<<<dim3(4, FDIM), 256>>>(x, emb, ipw, ipb);

    cudaLaunchAttribute attr[1];
    attr[0].id = cudaLaunchAttributeProgrammaticStreamSerialization;
    attr[0].val.programmaticStreamSerializationAllowed = 1;

    {   // stage B: PDL on stage A
        cudaLaunchConfig_t cfg = {};
        cfg.gridDim  = dim3(FH, BATCH / 128);
        cfg.blockDim = dim3(128);
        cfg.attrs = attr;
        cfg.numAttrs = 1;
        cudaLaunchKernelEx(&cfg, stageB);
    }
    {   // stage C: PDL on stage B (weight staging overlaps B's tail)
        cudaLaunchConfig_t cfg = {};
        cfg.gridDim  = dim3(BATCH / 16);
        cfg.blockDim = dim3(256);
        cfg.attrs = attr;
        cfg.numAttrs = 1;
        cudaLaunchKernelEx(&cfg, stageC, opw, opb, lw, lb, out);
    }
}